// round 16
// baseline (speedup 1.0000x reference)
#include <cuda_runtime.h>
#include <cuda_bf16.h>
#include <cuda_fp16.h>
#include <math_constants.h>
#include <cstdint>

// Problem constants
#define BATCH   2
#define CH      256
#define FRAMES  16
#define NPIX    4096
#define BF      32
#define HEADS   8
#define DH      32
#define QKV_M   768
#define XSTRIDE (FRAMES*NPIX)
#define CHUNKS  4
#define CK_N    1024
#define XELEMS  ((size_t)BATCH * CH * FRAMES * NPIX)   // 33,554,432
#define WELEMS  ((size_t)QKV_M * CH)                   // 196,608

// ---------------------------------------------------------------------------
// Scratch
// ---------------------------------------------------------------------------
__device__ __half g_xh[XELEMS];
__device__ __half g_wh[WELEMS];                    // W single fp16
__device__ __half g_qh[(size_t)BF * CH * NPIX];    // softmaxed q fp16
__device__ __half g_sh[(size_t)BF * CH * NPIX];    // exp(k) fp16
__device__ __half g_vh[(size_t)BF * CH * NPIX];    // v fp16
__device__ float  g_zp[(size_t)BF * 256 * 32];     // z partials [bi][row][nchunk]
__device__ float  g_ctxp[(size_t)CHUNKS * BF * HEADS * DH * DH];
__device__ __half g_wfh[(size_t)BF * CH * CH];     // Wf single fp16

__device__ __forceinline__ uint32_t smem_u32(const void* p) {
    uint32_t a;
    asm("{ .reg .u64 t; cvta.to.shared.u64 t, %1; cvt.u32.u64 %0, t; }" : "=r"(a) : "l"(p));
    return a;
}
__device__ __forceinline__ void cp16(uint32_t dst, const void* src) {
    asm volatile("cp.async.cg.shared.global [%0], [%1], 16;" :: "r"(dst), "l"(src) : "memory");
}
__device__ __forceinline__ void ldsm4(uint32_t* r, uint32_t addr) {
    asm volatile("ldmatrix.sync.aligned.m8n8.x4.shared.b16 {%0,%1,%2,%3}, [%4];"
                 : "=r"(r[0]), "=r"(r[1]), "=r"(r[2]), "=r"(r[3]) : "r"(addr));
}
__device__ __forceinline__ void ldsm4t(uint32_t* r, uint32_t addr) {
    asm volatile("ldmatrix.sync.aligned.m8n8.x4.trans.shared.b16 {%0,%1,%2,%3}, [%4];"
                 : "=r"(r[0]), "=r"(r[1]), "=r"(r[2]), "=r"(r[3]) : "r"(addr));
}
__device__ __forceinline__ void mma_fp16(float* c, const uint32_t* a, const uint32_t* b) {
    asm volatile("mma.sync.aligned.m16n8k16.row.col.f32.f16.f16.f32 "
                 "{%0,%1,%2,%3}, {%4,%5,%6,%7}, {%8,%9}, {%0,%1,%2,%3};"
                 : "+f"(c[0]), "+f"(c[1]), "+f"(c[2]), "+f"(c[3])
                 : "r"(a[0]), "r"(a[1]), "r"(a[2]), "r"(a[3]), "r"(b[0]), "r"(b[1]));
}
__device__ __forceinline__ void mma_fp16_2(float* c, const uint32_t* a,
                                           uint32_t b0, uint32_t b1) {
    asm volatile("mma.sync.aligned.m16n8k16.row.col.f32.f16.f16.f32 "
                 "{%0,%1,%2,%3}, {%4,%5,%6,%7}, {%8,%9}, {%0,%1,%2,%3};"
                 : "+f"(c[0]), "+f"(c[1]), "+f"(c[2]), "+f"(c[3])
                 : "r"(a[0]), "r"(a[1]), "r"(a[2]), "r"(a[3]), "r"(b0), "r"(b1));
}

// ---------------------------------------------------------------------------
// Merged split: x then W, fp32 -> single fp16, 8 elems/thread
// ---------------------------------------------------------------------------
__global__ void k_split_all(const float* __restrict__ x, const float* __restrict__ w,
                            __half* __restrict__ xh, __half* __restrict__ wh) {
    size_t i = ((size_t)blockIdx.x * 256 + threadIdx.x) * 8;
    const float* src;
    __half* dst;
    if (i < XELEMS) { src = x + i; dst = xh + i; }
    else            { size_t j = i - XELEMS; if (j >= WELEMS) return; src = w + j; dst = wh + j; }
    float4 v0 = *(const float4*)src;
    float4 v1 = *(const float4*)(src + 4);
    __half2* dp = (__half2*)dst;
    dp[0] = __half2(__float2half(v0.x), __float2half(v0.y));
    dp[1] = __half2(__float2half(v0.z), __float2half(v0.w));
    dp[2] = __half2(__float2half(v1.x), __float2half(v1.y));
    dp[3] = __half2(__float2half(v1.z), __float2half(v1.w));
}

// ---------------------------------------------------------------------------
// Streaming 1-product fp16 GEMM, 5-stage pipeline, 2 CTAs/SM.
// OUT_MODE=false: qkv. TILE_KIND by m-block:
//                 0=q (softmax->qh), 1=k (exp->sh + z partials), 2=v (vh).
// OUT_MODE=true : out = Wf @ qh + bias, scatter.
// ---------------------------------------------------------------------------
#define PA2    80                          // A row pitch (32 fp16 + 16B pad)
#define SZ_A2  (128 * PA2)                 // 10240
#define PB     272                         // B row pitch (128 fp16 + 16B pad)
#define SZ_B2  (32 * PB)                   // 8704
#define STG2   (SZ_A2 + SZ_B2)             // 18944
#define NSTAGE 5
#define SGEMM_SMEM (NSTAGE * STG2)         // 94720

template <bool OUT_MODE>
__global__ void __launch_bounds__(256, 2) k_sgemm(const __half* __restrict__ Ah_g,
                                                  const __half* __restrict__ Bh_g,
                                                  const float* __restrict__ bias,
                                                  float* __restrict__ outp,
                                                  __half* __restrict__ qout,
                                                  __half* __restrict__ shout,
                                                  __half* __restrict__ vhout,
                                                  float* __restrict__ zp) {
    extern __shared__ char smem[];
    const uint32_t sb0 = smem_u32(smem);
    int tid = threadIdx.x, w = tid >> 5, lane = tid & 31;
    int m0 = blockIdx.y * 128;
    int n0 = blockIdx.x * 128;
    int bi = blockIdx.z, b = bi >> 4, f = bi & 15;
    const int TILE_KIND = OUT_MODE ? 3 : (int)(blockIdx.y >> 1);

    const __half* Ah = Ah_g + (OUT_MODE ? (size_t)bi * CH * CH : 0);
    const size_t bstride = OUT_MODE ? (size_t)NPIX : (size_t)XSTRIDE;
    const __half* Bh = Bh_g + (OUT_MODE ? (size_t)bi * CH * NPIX
                                        : ((size_t)(b * CH) * FRAMES + f) * NPIX);

    auto loadStage = [&](int s, int kt) {
        uint32_t sb = sb0 + (uint32_t)s * STG2;
        #pragma unroll
        for (int i = 0; i < 2; i++) {
            int ch = tid + i * 256;
            int r = ch >> 2, c = ch & 3;
            cp16(sb + r * PA2 + c * 16,
                 Ah + (size_t)(m0 + r) * CH + kt * 32 + c * 8);
        }
        #pragma unroll
        for (int i = 0; i < 2; i++) {
            int ch = tid + i * 256;
            int r = ch >> 4, c = ch & 15;
            cp16(sb + SZ_A2 + r * PB + c * 16,
                 Bh + (size_t)(kt * 32 + r) * bstride + n0 + c * 8);
        }
        asm volatile("cp.async.commit_group;" ::: "memory");
    };

    int wm = (w & 1) * 64;
    int wn = (w >> 1) * 32;
    uint32_t aRel = (uint32_t)(wm + (lane & 15)) * PA2 + (uint32_t)(lane >> 4) * 16;
    uint32_t bRel = SZ_A2 + (uint32_t)(lane & 15) * PB + (uint32_t)(lane >> 4) * 16
                  + (uint32_t)wn * 2;

    float acc[4][4][4];
    #pragma unroll
    for (int i = 0; i < 4; i++)
        #pragma unroll
        for (int j = 0; j < 4; j++)
            #pragma unroll
            for (int r = 0; r < 4; r++) acc[i][j][r] = 0.f;

    loadStage(0, 0);
    loadStage(1, 1);
    loadStage(2, 2);
    loadStage(3, 3);

    #pragma unroll
    for (int kt = 0; kt < 8; kt++) {
        asm volatile("cp.async.wait_group 3;" ::: "memory");
        __syncthreads();
        if (kt < 4) loadStage((kt + 4) % NSTAGE, kt + 4);
        else asm volatile("cp.async.commit_group;" ::: "memory");

        uint32_t sb = sb0 + (uint32_t)(kt % NSTAGE) * STG2;
        #pragma unroll
        for (int ks = 0; ks < 2; ks++) {
            uint32_t aHf[4][4], bHf[2][4];
            #pragma unroll
            for (int mi = 0; mi < 4; mi++)
                ldsm4(aHf[mi], sb + aRel + (uint32_t)(mi * 16) * PA2 + ks * 32);
            #pragma unroll
            for (int ng = 0; ng < 2; ng++)
                ldsm4t(bHf[ng], sb + bRel + (uint32_t)(ks * 16) * PB + ng * 32);
            #pragma unroll
            for (int mi = 0; mi < 4; mi++)
                #pragma unroll
                for (int ni = 0; ni < 4; ni++)
                    mma_fp16(acc[mi][ni], aHf[mi], &bHf[ni >> 1][(ni & 1) * 2]);
        }
    }

    // ---------------- epilogues ----------------
    if (TILE_KIND == 0) {
        // q: fused softmax over d (head = 2 consecutive mi), store fp16
        #pragma unroll
        for (int h = 0; h < 2; h++) {
            int mi0 = 2 * h, mi1 = 2 * h + 1;
            #pragma unroll
            for (int ni = 0; ni < 4; ni++) {
                #pragma unroll
                for (int p = 0; p < 2; p++) {
                    float v0 = acc[mi0][ni][p],     v1 = acc[mi0][ni][p + 2];
                    float v2 = acc[mi1][ni][p],     v3 = acc[mi1][ni][p + 2];
                    float mx = fmaxf(fmaxf(v0, v1), fmaxf(v2, v3));
                    mx = fmaxf(mx, __shfl_xor_sync(0xffffffffu, mx, 4));
                    mx = fmaxf(mx, __shfl_xor_sync(0xffffffffu, mx, 8));
                    mx = fmaxf(mx, __shfl_xor_sync(0xffffffffu, mx, 16));
                    v0 = __expf(v0 - mx); v1 = __expf(v1 - mx);
                    v2 = __expf(v2 - mx); v3 = __expf(v3 - mx);
                    float s = v0 + v1 + v2 + v3;
                    s += __shfl_xor_sync(0xffffffffu, s, 4);
                    s += __shfl_xor_sync(0xffffffffu, s, 8);
                    s += __shfl_xor_sync(0xffffffffu, s, 16);
                    float inv = 0.17677669529663687f / s;
                    acc[mi0][ni][p]     = v0 * inv;
                    acc[mi0][ni][p + 2] = v1 * inv;
                    acc[mi1][ni][p]     = v2 * inv;
                    acc[mi1][ni][p + 2] = v3 * inv;
                }
            }
        }
        __half* qbase = qout + (size_t)bi * CH * NPIX;
        #pragma unroll
        for (int mi = 0; mi < 4; mi++)
            #pragma unroll
            for (int ni = 0; ni < 4; ni++) {
                int r0 = m0 + wm + mi * 16 + (lane >> 2);
                int cc = n0 + wn + ni * 8 + (lane & 3) * 2;
                *(__half2*)(qbase + (size_t)r0 * NPIX + cc) =
                    __half2(__float2half(acc[mi][ni][0]), __float2half(acc[mi][ni][1]));
                *(__half2*)(qbase + (size_t)(r0 + 8) * NPIX + cc) =
                    __half2(__float2half(acc[mi][ni][2]), __float2half(acc[mi][ni][3]));
            }
    } else if (TILE_KIND == 1) {
        // k: exp -> single fp16 + z partials
        __half* shb = shout + (size_t)bi * CH * NPIX;
        float zloc[4][2];
        #pragma unroll
        for (int mi = 0; mi < 4; mi++) { zloc[mi][0] = 0.f; zloc[mi][1] = 0.f; }
        #pragma unroll
        for (int mi = 0; mi < 4; mi++)
            #pragma unroll
            for (int ni = 0; ni < 4; ni++) {
                int r0 = m0 - 256 + wm + mi * 16 + (lane >> 2);
                int cc = n0 + wn + ni * 8 + (lane & 3) * 2;
                #pragma unroll
                for (int rr = 0; rr < 2; rr++) {
                    float e0 = __expf(acc[mi][ni][rr * 2]);
                    float e1 = __expf(acc[mi][ni][rr * 2 + 1]);
                    zloc[mi][rr] += e0 + e1;
                    *(__half2*)(shb + (size_t)(r0 + rr * 8) * NPIX + cc) =
                        __half2(__float2half(e0), __float2half(e1));
                }
            }
        #pragma unroll
        for (int mi = 0; mi < 4; mi++)
            #pragma unroll
            for (int rr = 0; rr < 2; rr++) {
                zloc[mi][rr] += __shfl_xor_sync(0xffffffffu, zloc[mi][rr], 1);
                zloc[mi][rr] += __shfl_xor_sync(0xffffffffu, zloc[mi][rr], 2);
            }
        __syncthreads();
        float* zs = (float*)smem;              // [128][4]
        if ((lane & 3) == 0) {
            #pragma unroll
            for (int mi = 0; mi < 4; mi++)
                #pragma unroll
                for (int rr = 0; rr < 2; rr++) {
                    int row = wm + mi * 16 + (lane >> 2) + rr * 8;
                    zs[row * 4 + (w >> 1)] = zloc[mi][rr];
                }
        }
        __syncthreads();
        if (tid < 128) {
            float z = zs[tid * 4] + zs[tid * 4 + 1] + zs[tid * 4 + 2] + zs[tid * 4 + 3];
            zp[((size_t)bi * 256 + (m0 - 256) + tid) * 32 + blockIdx.x] = z;
        }
    } else if (TILE_KIND == 2) {
        // v: single fp16
        __half* vhb = vhout + (size_t)bi * CH * NPIX;
        #pragma unroll
        for (int mi = 0; mi < 4; mi++)
            #pragma unroll
            for (int ni = 0; ni < 4; ni++) {
                int r0 = m0 - 512 + wm + mi * 16 + (lane >> 2);
                int cc = n0 + wn + ni * 8 + (lane & 3) * 2;
                #pragma unroll
                for (int rr = 0; rr < 2; rr++) {
                    *(__half2*)(vhb + (size_t)(r0 + rr * 8) * NPIX + cc) =
                        __half2(__float2half(acc[mi][ni][rr * 2]),
                                __float2half(acc[mi][ni][rr * 2 + 1]));
                }
            }
    } else {
        // out: + bias, scatter
        #pragma unroll
        for (int mi = 0; mi < 4; mi++)
            #pragma unroll
            for (int ni = 0; ni < 4; ni++) {
                int r0 = m0 + wm + mi * 16 + (lane >> 2);
                int r1 = r0 + 8;
                int cc = n0 + wn + ni * 8 + (lane & 3) * 2;
                float b0 = bias[r0], b1 = bias[r1];
                float* p0 = outp + ((size_t)(b * CH + r0) * FRAMES + f) * NPIX + cc;
                float* p1 = outp + ((size_t)(b * CH + r1) * FRAMES + f) * NPIX + cc;
                *(float2*)p0 = make_float2(acc[mi][ni][0] + b0, acc[mi][ni][1] + b0);
                *(float2*)p1 = make_float2(acc[mi][ni][2] + b1, acc[mi][ni][3] + b1);
            }
    }
}

// ---------------------------------------------------------------------------
// Tensor-core context: P[d][e] = sum_n S[d,n]*v[e,n], S and v single fp16.
// Grid (HEADS, BF, CHUNKS); 6-stage cp.async, 1-product mma, partials to gmem.
// ---------------------------------------------------------------------------
#define C2P    272
#define C2SZ   (32 * C2P)                // 8704
#define C2STG  (2 * C2SZ)                // 17408
#define CNSTG  6
#define CTX2_SMEM (CNSTG * C2STG)        // 104448

__global__ void __launch_bounds__(256, 2) k_context_tc(const __half* __restrict__ sh,
                                                       const __half* __restrict__ vh,
                                                       float* __restrict__ ctxp) {
    extern __shared__ char smem[];
    const uint32_t sb0 = smem_u32(smem);
    int tid = threadIdx.x, w = tid >> 5, lane = tid & 31;
    int head = blockIdx.x, bi = blockIdx.y, chunk = blockIdx.z;
    int bh = bi * HEADS + head;

    size_t base = ((size_t)bi * CH + head * DH) * NPIX + chunk * CK_N;
    const __half* s_h = sh + base;
    const __half* v_h = vh + base;

    auto loadT = [&](int s, int p) {
        int n0 = p * 128;
        uint32_t sb = sb0 + (uint32_t)s * C2STG;
        #pragma unroll
        for (int i = 0; i < 2; i++) {
            int ch = tid + i * 256;
            int r = ch >> 4, c = ch & 15;
            size_t go = (size_t)r * NPIX + n0 + c * 8;
            uint32_t d = sb + r * C2P + c * 16;
            cp16(d, s_h + go);
            cp16(d + C2SZ, v_h + go);
        }
        asm volatile("cp.async.commit_group;" ::: "memory");
    };

    float acc[2][4][4];
    #pragma unroll
    for (int i = 0; i < 2; i++)
        #pragma unroll
        for (int j = 0; j < 4; j++)
            #pragma unroll
            for (int r = 0; r < 4; r++) acc[i][j][r] = 0.f;

    loadT(0, 0);
    loadT(1, 1);
    loadT(2, 2);
    loadT(3, 3);
    loadT(4, 4);

    uint32_t cb = (uint32_t)w * 32 + (uint32_t)(lane >> 4) * 16;

    #pragma unroll
    for (int p = 0; p < 8; p++) {
        asm volatile("cp.async.wait_group 4;" ::: "memory");
        __syncthreads();
        if (p < 3) loadT((p + 5) % CNSTG, p + 5);
        else asm volatile("cp.async.commit_group;" ::: "memory");

        uint32_t sb = sb0 + (uint32_t)(p % CNSTG) * C2STG;
        uint32_t shf[2][4];
        #pragma unroll
        for (int mi = 0; mi < 2; mi++)
            ldsm4(shf[mi], sb + (uint32_t)(mi * 16 + (lane & 15)) * C2P + cb);
        #pragma unroll
        for (int ei = 0; ei < 2; ei++) {
            uint32_t vhf[4];
            ldsm4(vhf, sb + C2SZ + (uint32_t)(ei * 16 + (lane & 15)) * C2P + cb);
            #pragma unroll
            for (int pick = 0; pick < 2; pick++) {
                int nt = ei * 2 + pick;
                #pragma unroll
                for (int mi = 0; mi < 2; mi++)
                    mma_fp16_2(acc[mi][nt], shf[mi], vhf[pick], vhf[pick + 2]);
            }
        }
    }

    // reduce across 8 warps via smem (overlays stages)
    __syncthreads();
    float* stage = (float*)smem + w * 1056;    // 32 x 33 per warp
    #pragma unroll
    for (int mi = 0; mi < 2; mi++)
        #pragma unroll
        for (int nt = 0; nt < 4; nt++) {
            int r0 = mi * 16 + (lane >> 2);
            int c0 = nt * 8 + (lane & 3) * 2;
            stage[r0 * 33 + c0]           = acc[mi][nt][0];
            stage[r0 * 33 + c0 + 1]       = acc[mi][nt][1];
            stage[(r0 + 8) * 33 + c0]     = acc[mi][nt][2];
            stage[(r0 + 8) * 33 + c0 + 1] = acc[mi][nt][3];
        }
    __syncthreads();
    {
        float* basep = (float*)smem;
        int j0 = tid * 4;
        int d = j0 >> 5, e = j0 & 31;
        float4 s = make_float4(0.f, 0.f, 0.f, 0.f);
        #pragma unroll
        for (int ww = 0; ww < 8; ww++) {
            float* p2 = basep + ww * 1056 + d * 33 + e;
            s.x += p2[0]; s.y += p2[1]; s.z += p2[2]; s.w += p2[3];
        }
        *(float4*)(ctxp + ((size_t)chunk * 256 + bh) * 1024 + j0) = s;
    }
}

// ---------------------------------------------------------------------------
// fused weight: ctx = (sum_c P_c) / z, Wf = w_out(head slice) @ ctx^T -> fp16
// Parallel z (8 thr/row, float4) + float4 ctxp reduction. One block/(head,bi).
// ---------------------------------------------------------------------------
__global__ void __launch_bounds__(256) k_wf(const float* __restrict__ w_out,
                                            const float* __restrict__ ctxp,
                                            const float* __restrict__ zp,
                                            __half* __restrict__ wfh) {
    int head = blockIdx.x, bi = blockIdx.y;
    int bh = bi * HEADS + head;
    __shared__ float cs[DH][33];
    __shared__ float z_s[DH];
    int tid = threadIdx.x;

    // z: 32 rows x 32 chunk-partials; 8 threads/row, float4 each + shfl reduce
    {
        int r = tid >> 3, c4 = (tid & 7) * 4;
        const float* zr = zp + ((size_t)bi * 256 + head * DH + r) * 32 + c4;
        float4 v = *(const float4*)zr;
        float s = v.x + v.y + v.z + v.w;
        s += __shfl_xor_sync(0xffffffffu, s, 1);
        s += __shfl_xor_sync(0xffffffffu, s, 2);
        s += __shfl_xor_sync(0xffffffffu, s, 4);
        if ((tid & 7) == 0) z_s[r] = s;
    }
    __syncthreads();

    // ctx: sum 4 chunk partials (float4 per thread), divide by z
    {
        int j0 = tid * 4;
        int d = j0 >> 5, e = j0 & 31;
        float4 s = make_float4(0.f, 0.f, 0.f, 0.f);
        #pragma unroll
        for (int c = 0; c < CHUNKS; c++) {
            float4 t = *(const float4*)(ctxp + ((size_t)c * 256 + bh) * 1024 + j0);
            s.x += t.x; s.y += t.y; s.z += t.z; s.w += t.w;
        }
        float inv = 1.0f / z_s[d];
        cs[d][e]     = s.x * inv;
        cs[d][e + 1] = s.y * inv;
        cs[d][e + 2] = s.z * inv;
        cs[d][e + 3] = s.w * inv;
    }
    __syncthreads();

    int d = tid & 31, og = tid >> 5;
    for (int o = og; o < CH; o += 8) {
        const float* wrow = w_out + (size_t)o * CH + head * DH;
        float acc = 0.f;
        #pragma unroll
        for (int e = 0; e < DH; e++) acc += wrow[e] * cs[d][e];
        wfh[(size_t)bi * CH * CH + (size_t)o * CH + head * DH + d] = __float2half(acc);
    }
}

// ---------------------------------------------------------------------------
extern "C" void kernel_launch(void* const* d_in, const int* in_sizes, int n_in,
                              void* d_out, int out_size) {
    const float* x     = (const float*)d_in[0];
    const float* w_qkv = (const float*)d_in[1];
    const float* w_out = (const float*)d_in[2];
    const float* b_out = (const float*)d_in[3];
    float* out = (float*)d_out;

    __half *xh, *wh, *qh, *sh, *vh, *wfh;
    float *ctxp, *zp;
    cudaGetSymbolAddress((void**)&xh,   g_xh);
    cudaGetSymbolAddress((void**)&wh,   g_wh);
    cudaGetSymbolAddress((void**)&qh,   g_qh);
    cudaGetSymbolAddress((void**)&sh,   g_sh);
    cudaGetSymbolAddress((void**)&vh,   g_vh);
    cudaGetSymbolAddress((void**)&ctxp, g_ctxp);
    cudaGetSymbolAddress((void**)&zp,   g_zp);
    cudaGetSymbolAddress((void**)&wfh,  g_wfh);

    cudaFuncSetAttribute(k_sgemm<false>, cudaFuncAttributeMaxDynamicSharedMemorySize, SGEMM_SMEM);
    cudaFuncSetAttribute(k_sgemm<true>,  cudaFuncAttributeMaxDynamicSharedMemorySize, SGEMM_SMEM);
    cudaFuncSetAttribute(k_context_tc,   cudaFuncAttributeMaxDynamicSharedMemorySize, CTX2_SMEM);

    // 0. merged splits (single fp16), 8 elems/thread
    int split_blocks = (int)((XELEMS + WELEMS) / 2048);
    k_split_all<<<split_blocks, 256>>>(x, w_qkv, xh, wh);
    // 1. QKV GEMM (1-product); epilogues: q softmax, k exp + z, v
    k_sgemm<false><<<dim3(NPIX / 128, QKV_M / 128, BF), 256, SGEMM_SMEM>>>(
        wh, xh, nullptr, nullptr, qh, sh, vh, zp);
    // 2. tensor-core context partials (1-product, 6-stage)
    k_context_tc<<<dim3(HEADS, BF, CHUNKS), 256, CTX2_SMEM>>>(sh, vh, ctxp);
    // 3. fused weight -> single fp16
    k_wf<<<dim3(HEADS, BF), 256>>>(w_out, ctxp, zp, wfh);
    // 4. output GEMM (1-product) + bias + scatter
    k_sgemm<true><<<dim3(NPIX / 128, CH / 128, BF), 256, SGEMM_SMEM>>>(
        wfh, qh, b_out, out, nullptr, nullptr, nullptr, nullptr);
}

// round 17
// speedup vs baseline: 1.0416x; 1.0416x over previous
#include <cuda_runtime.h>
#include <cuda_bf16.h>
#include <cuda_fp16.h>
#include <math_constants.h>
#include <cstdint>

// Problem constants
#define BATCH   2
#define CH      256
#define FRAMES  16
#define NPIX    4096
#define BF      32
#define HEADS   8
#define DH      32
#define QKV_M   768
#define XSTRIDE (FRAMES*NPIX)
#define CHUNKS  4
#define CK_N    1024
#define XELEMS  ((size_t)BATCH * CH * FRAMES * NPIX)   // 33,554,432
#define WELEMS  ((size_t)QKV_M * CH)                   // 196,608

// ---------------------------------------------------------------------------
// Scratch
// ---------------------------------------------------------------------------
__device__ __half g_xh[XELEMS];
__device__ __half g_wh[WELEMS];                    // W single fp16
__device__ __half g_qh[(size_t)BF * CH * NPIX];    // softmaxed q fp16
__device__ __half g_sh[(size_t)BF * CH * NPIX];    // exp(k) fp16
__device__ __half g_vh[(size_t)BF * CH * NPIX];    // v fp16
__device__ float  g_zp[(size_t)BF * 256 * 32];     // z partials [bi][row][nchunk]
__device__ float  g_ctxp[(size_t)CHUNKS * BF * HEADS * DH * DH];
__device__ __half g_wfh[(size_t)BF * CH * CH];     // Wf single fp16

__device__ __forceinline__ uint32_t smem_u32(const void* p) {
    uint32_t a;
    asm("{ .reg .u64 t; cvta.to.shared.u64 t, %1; cvt.u32.u64 %0, t; }" : "=r"(a) : "l"(p));
    return a;
}
__device__ __forceinline__ void cp16(uint32_t dst, const void* src) {
    asm volatile("cp.async.cg.shared.global [%0], [%1], 16;" :: "r"(dst), "l"(src) : "memory");
}
__device__ __forceinline__ void ldsm4(uint32_t* r, uint32_t addr) {
    asm volatile("ldmatrix.sync.aligned.m8n8.x4.shared.b16 {%0,%1,%2,%3}, [%4];"
                 : "=r"(r[0]), "=r"(r[1]), "=r"(r[2]), "=r"(r[3]) : "r"(addr));
}
__device__ __forceinline__ void ldsm4t(uint32_t* r, uint32_t addr) {
    asm volatile("ldmatrix.sync.aligned.m8n8.x4.trans.shared.b16 {%0,%1,%2,%3}, [%4];"
                 : "=r"(r[0]), "=r"(r[1]), "=r"(r[2]), "=r"(r[3]) : "r"(addr));
}
__device__ __forceinline__ void mma_fp16(float* c, const uint32_t* a, const uint32_t* b) {
    asm volatile("mma.sync.aligned.m16n8k16.row.col.f32.f16.f16.f32 "
                 "{%0,%1,%2,%3}, {%4,%5,%6,%7}, {%8,%9}, {%0,%1,%2,%3};"
                 : "+f"(c[0]), "+f"(c[1]), "+f"(c[2]), "+f"(c[3])
                 : "r"(a[0]), "r"(a[1]), "r"(a[2]), "r"(a[3]), "r"(b[0]), "r"(b[1]));
}
__device__ __forceinline__ void mma_fp16_2(float* c, const uint32_t* a,
                                           uint32_t b0, uint32_t b1) {
    asm volatile("mma.sync.aligned.m16n8k16.row.col.f32.f16.f16.f32 "
                 "{%0,%1,%2,%3}, {%4,%5,%6,%7}, {%8,%9}, {%0,%1,%2,%3};"
                 : "+f"(c[0]), "+f"(c[1]), "+f"(c[2]), "+f"(c[3])
                 : "r"(a[0]), "r"(a[1]), "r"(a[2]), "r"(a[3]), "r"(b0), "r"(b1));
}

// ---------------------------------------------------------------------------
// Merged split: x then W, fp32 -> single fp16, 8 elems/thread
// ---------------------------------------------------------------------------
__global__ void k_split_all(const float* __restrict__ x, const float* __restrict__ w,
                            __half* __restrict__ xh, __half* __restrict__ wh) {
    size_t i = ((size_t)blockIdx.x * 256 + threadIdx.x) * 8;
    const float* src;
    __half* dst;
    if (i < XELEMS) { src = x + i; dst = xh + i; }
    else            { size_t j = i - XELEMS; if (j >= WELEMS) return; src = w + j; dst = wh + j; }
    float4 v0 = *(const float4*)src;
    float4 v1 = *(const float4*)(src + 4);
    __half2* dp = (__half2*)dst;
    dp[0] = __half2(__float2half(v0.x), __float2half(v0.y));
    dp[1] = __half2(__float2half(v0.z), __float2half(v0.w));
    dp[2] = __half2(__float2half(v1.x), __float2half(v1.y));
    dp[3] = __half2(__float2half(v1.z), __float2half(v1.w));
}

// ---------------------------------------------------------------------------
// Streaming 1-product fp16 GEMM, 5-stage pipeline, 2 CTAs/SM.
// OUT_MODE=false: qkv. TILE_KIND by m-block:
//                 0=q (softmax->qh), 1=k (exp->sh + z partials), 2=v (vh).
// OUT_MODE=true : out = Wf @ qh + bias, scatter.
// ---------------------------------------------------------------------------
#define PA2    80                          // A row pitch (32 fp16 + 16B pad)
#define SZ_A2  (128 * PA2)                 // 10240
#define PB     272                         // B row pitch (128 fp16 + 16B pad)
#define SZ_B2  (32 * PB)                   // 8704
#define STG2   (SZ_A2 + SZ_B2)             // 18944
#define NSTAGE 5
#define SGEMM_SMEM (NSTAGE * STG2)         // 94720

template <bool OUT_MODE>
__global__ void __launch_bounds__(256, 2) k_sgemm(const __half* __restrict__ Ah_g,
                                                  const __half* __restrict__ Bh_g,
                                                  const float* __restrict__ bias,
                                                  float* __restrict__ outp,
                                                  __half* __restrict__ qout,
                                                  __half* __restrict__ shout,
                                                  __half* __restrict__ vhout,
                                                  float* __restrict__ zp) {
    extern __shared__ char smem[];
    const uint32_t sb0 = smem_u32(smem);
    int tid = threadIdx.x, w = tid >> 5, lane = tid & 31;
    int m0 = blockIdx.y * 128;
    int n0 = blockIdx.x * 128;
    int bi = blockIdx.z, b = bi >> 4, f = bi & 15;
    const int TILE_KIND = OUT_MODE ? 3 : (int)(blockIdx.y >> 1);

    const __half* Ah = Ah_g + (OUT_MODE ? (size_t)bi * CH * CH : 0);
    const size_t bstride = OUT_MODE ? (size_t)NPIX : (size_t)XSTRIDE;
    const __half* Bh = Bh_g + (OUT_MODE ? (size_t)bi * CH * NPIX
                                        : ((size_t)(b * CH) * FRAMES + f) * NPIX);

    auto loadStage = [&](int s, int kt) {
        uint32_t sb = sb0 + (uint32_t)s * STG2;
        #pragma unroll
        for (int i = 0; i < 2; i++) {
            int ch = tid + i * 256;
            int r = ch >> 2, c = ch & 3;
            cp16(sb + r * PA2 + c * 16,
                 Ah + (size_t)(m0 + r) * CH + kt * 32 + c * 8);
        }
        #pragma unroll
        for (int i = 0; i < 2; i++) {
            int ch = tid + i * 256;
            int r = ch >> 4, c = ch & 15;
            cp16(sb + SZ_A2 + r * PB + c * 16,
                 Bh + (size_t)(kt * 32 + r) * bstride + n0 + c * 8);
        }
        asm volatile("cp.async.commit_group;" ::: "memory");
    };

    int wm = (w & 1) * 64;
    int wn = (w >> 1) * 32;
    uint32_t aRel = (uint32_t)(wm + (lane & 15)) * PA2 + (uint32_t)(lane >> 4) * 16;
    uint32_t bRel = SZ_A2 + (uint32_t)(lane & 15) * PB + (uint32_t)(lane >> 4) * 16
                  + (uint32_t)wn * 2;

    float acc[4][4][4];
    #pragma unroll
    for (int i = 0; i < 4; i++)
        #pragma unroll
        for (int j = 0; j < 4; j++)
            #pragma unroll
            for (int r = 0; r < 4; r++) acc[i][j][r] = 0.f;

    loadStage(0, 0);
    loadStage(1, 1);
    loadStage(2, 2);
    loadStage(3, 3);

    #pragma unroll
    for (int kt = 0; kt < 8; kt++) {
        asm volatile("cp.async.wait_group 3;" ::: "memory");
        __syncthreads();
        if (kt < 4) loadStage((kt + 4) % NSTAGE, kt + 4);
        else asm volatile("cp.async.commit_group;" ::: "memory");

        uint32_t sb = sb0 + (uint32_t)(kt % NSTAGE) * STG2;
        #pragma unroll
        for (int ks = 0; ks < 2; ks++) {
            uint32_t aHf[4][4], bHf[2][4];
            #pragma unroll
            for (int mi = 0; mi < 4; mi++)
                ldsm4(aHf[mi], sb + aRel + (uint32_t)(mi * 16) * PA2 + ks * 32);
            #pragma unroll
            for (int ng = 0; ng < 2; ng++)
                ldsm4t(bHf[ng], sb + bRel + (uint32_t)(ks * 16) * PB + ng * 32);
            #pragma unroll
            for (int mi = 0; mi < 4; mi++)
                #pragma unroll
                for (int ni = 0; ni < 4; ni++)
                    mma_fp16(acc[mi][ni], aHf[mi], &bHf[ni >> 1][(ni & 1) * 2]);
        }
    }

    // ---------------- epilogues ----------------
    if (TILE_KIND == 0) {
        // q: fused softmax over d (head = 2 consecutive mi), store fp16
        #pragma unroll
        for (int h = 0; h < 2; h++) {
            int mi0 = 2 * h, mi1 = 2 * h + 1;
            #pragma unroll
            for (int ni = 0; ni < 4; ni++) {
                #pragma unroll
                for (int p = 0; p < 2; p++) {
                    float v0 = acc[mi0][ni][p],     v1 = acc[mi0][ni][p + 2];
                    float v2 = acc[mi1][ni][p],     v3 = acc[mi1][ni][p + 2];
                    float mx = fmaxf(fmaxf(v0, v1), fmaxf(v2, v3));
                    mx = fmaxf(mx, __shfl_xor_sync(0xffffffffu, mx, 4));
                    mx = fmaxf(mx, __shfl_xor_sync(0xffffffffu, mx, 8));
                    mx = fmaxf(mx, __shfl_xor_sync(0xffffffffu, mx, 16));
                    v0 = __expf(v0 - mx); v1 = __expf(v1 - mx);
                    v2 = __expf(v2 - mx); v3 = __expf(v3 - mx);
                    float s = v0 + v1 + v2 + v3;
                    s += __shfl_xor_sync(0xffffffffu, s, 4);
                    s += __shfl_xor_sync(0xffffffffu, s, 8);
                    s += __shfl_xor_sync(0xffffffffu, s, 16);
                    float inv = 0.17677669529663687f / s;
                    acc[mi0][ni][p]     = v0 * inv;
                    acc[mi0][ni][p + 2] = v1 * inv;
                    acc[mi1][ni][p]     = v2 * inv;
                    acc[mi1][ni][p + 2] = v3 * inv;
                }
            }
        }
        __half* qbase = qout + (size_t)bi * CH * NPIX;
        #pragma unroll
        for (int mi = 0; mi < 4; mi++)
            #pragma unroll
            for (int ni = 0; ni < 4; ni++) {
                int r0 = m0 + wm + mi * 16 + (lane >> 2);
                int cc = n0 + wn + ni * 8 + (lane & 3) * 2;
                *(__half2*)(qbase + (size_t)r0 * NPIX + cc) =
                    __half2(__float2half(acc[mi][ni][0]), __float2half(acc[mi][ni][1]));
                *(__half2*)(qbase + (size_t)(r0 + 8) * NPIX + cc) =
                    __half2(__float2half(acc[mi][ni][2]), __float2half(acc[mi][ni][3]));
            }
    } else if (TILE_KIND == 1) {
        // k: exp -> single fp16 + z partials
        __half* shb = shout + (size_t)bi * CH * NPIX;
        float zloc[4][2];
        #pragma unroll
        for (int mi = 0; mi < 4; mi++) { zloc[mi][0] = 0.f; zloc[mi][1] = 0.f; }
        #pragma unroll
        for (int mi = 0; mi < 4; mi++)
            #pragma unroll
            for (int ni = 0; ni < 4; ni++) {
                int r0 = m0 - 256 + wm + mi * 16 + (lane >> 2);
                int cc = n0 + wn + ni * 8 + (lane & 3) * 2;
                #pragma unroll
                for (int rr = 0; rr < 2; rr++) {
                    float e0 = __expf(acc[mi][ni][rr * 2]);
                    float e1 = __expf(acc[mi][ni][rr * 2 + 1]);
                    zloc[mi][rr] += e0 + e1;
                    *(__half2*)(shb + (size_t)(r0 + rr * 8) * NPIX + cc) =
                        __half2(__float2half(e0), __float2half(e1));
                }
            }
        #pragma unroll
        for (int mi = 0; mi < 4; mi++)
            #pragma unroll
            for (int rr = 0; rr < 2; rr++) {
                zloc[mi][rr] += __shfl_xor_sync(0xffffffffu, zloc[mi][rr], 1);
                zloc[mi][rr] += __shfl_xor_sync(0xffffffffu, zloc[mi][rr], 2);
            }
        __syncthreads();
        float* zs = (float*)smem;              // [128][4]
        if ((lane & 3) == 0) {
            #pragma unroll
            for (int mi = 0; mi < 4; mi++)
                #pragma unroll
                for (int rr = 0; rr < 2; rr++) {
                    int row = wm + mi * 16 + (lane >> 2) + rr * 8;
                    zs[row * 4 + (w >> 1)] = zloc[mi][rr];
                }
        }
        __syncthreads();
        if (tid < 128) {
            float z = zs[tid * 4] + zs[tid * 4 + 1] + zs[tid * 4 + 2] + zs[tid * 4 + 3];
            zp[((size_t)bi * 256 + (m0 - 256) + tid) * 32 + blockIdx.x] = z;
        }
    } else if (TILE_KIND == 2) {
        // v: single fp16
        __half* vhb = vhout + (size_t)bi * CH * NPIX;
        #pragma unroll
        for (int mi = 0; mi < 4; mi++)
            #pragma unroll
            for (int ni = 0; ni < 4; ni++) {
                int r0 = m0 - 512 + wm + mi * 16 + (lane >> 2);
                int cc = n0 + wn + ni * 8 + (lane & 3) * 2;
                #pragma unroll
                for (int rr = 0; rr < 2; rr++) {
                    *(__half2*)(vhb + (size_t)(r0 + rr * 8) * NPIX + cc) =
                        __half2(__float2half(acc[mi][ni][rr * 2]),
                                __float2half(acc[mi][ni][rr * 2 + 1]));
                }
            }
    } else {
        // out: + bias, scatter
        #pragma unroll
        for (int mi = 0; mi < 4; mi++)
            #pragma unroll
            for (int ni = 0; ni < 4; ni++) {
                int r0 = m0 + wm + mi * 16 + (lane >> 2);
                int r1 = r0 + 8;
                int cc = n0 + wn + ni * 8 + (lane & 3) * 2;
                float b0 = bias[r0], b1 = bias[r1];
                float* p0 = outp + ((size_t)(b * CH + r0) * FRAMES + f) * NPIX + cc;
                float* p1 = outp + ((size_t)(b * CH + r1) * FRAMES + f) * NPIX + cc;
                *(float2*)p0 = make_float2(acc[mi][ni][0] + b0, acc[mi][ni][1] + b0);
                *(float2*)p1 = make_float2(acc[mi][ni][2] + b1, acc[mi][ni][3] + b1);
            }
    }
}

// ---------------------------------------------------------------------------
// Tensor-core context: P[d][e] = sum_n S[d,n]*v[e,n], S and v single fp16.
// Grid (HEADS, BF, CHUNKS); 6-stage cp.async, 1-product mma, partials to gmem.
// ---------------------------------------------------------------------------
#define C2P    272
#define C2SZ   (32 * C2P)                // 8704
#define C2STG  (2 * C2SZ)                // 17408
#define CNSTG  6
#define CTX2_SMEM (CNSTG * C2STG)        // 104448

__global__ void __launch_bounds__(256, 2) k_context_tc(const __half* __restrict__ sh,
                                                       const __half* __restrict__ vh,
                                                       float* __restrict__ ctxp) {
    extern __shared__ char smem[];
    const uint32_t sb0 = smem_u32(smem);
    int tid = threadIdx.x, w = tid >> 5, lane = tid & 31;
    int head = blockIdx.x, bi = blockIdx.y, chunk = blockIdx.z;
    int bh = bi * HEADS + head;

    size_t base = ((size_t)bi * CH + head * DH) * NPIX + chunk * CK_N;
    const __half* s_h = sh + base;
    const __half* v_h = vh + base;

    auto loadT = [&](int s, int p) {
        int n0 = p * 128;
        uint32_t sb = sb0 + (uint32_t)s * C2STG;
        #pragma unroll
        for (int i = 0; i < 2; i++) {
            int ch = tid + i * 256;
            int r = ch >> 4, c = ch & 15;
            size_t go = (size_t)r * NPIX + n0 + c * 8;
            uint32_t d = sb + r * C2P + c * 16;
            cp16(d, s_h + go);
            cp16(d + C2SZ, v_h + go);
        }
        asm volatile("cp.async.commit_group;" ::: "memory");
    };

    float acc[2][4][4];
    #pragma unroll
    for (int i = 0; i < 2; i++)
        #pragma unroll
        for (int j = 0; j < 4; j++)
            #pragma unroll
            for (int r = 0; r < 4; r++) acc[i][j][r] = 0.f;

    loadT(0, 0);
    loadT(1, 1);
    loadT(2, 2);
    loadT(3, 3);
    loadT(4, 4);

    uint32_t cb = (uint32_t)w * 32 + (uint32_t)(lane >> 4) * 16;

    #pragma unroll
    for (int p = 0; p < 8; p++) {
        asm volatile("cp.async.wait_group 4;" ::: "memory");
        __syncthreads();
        if (p < 3) loadT((p + 5) % CNSTG, p + 5);
        else asm volatile("cp.async.commit_group;" ::: "memory");

        uint32_t sb = sb0 + (uint32_t)(p % CNSTG) * C2STG;
        uint32_t shf[2][4];
        #pragma unroll
        for (int mi = 0; mi < 2; mi++)
            ldsm4(shf[mi], sb + (uint32_t)(mi * 16 + (lane & 15)) * C2P + cb);
        #pragma unroll
        for (int ei = 0; ei < 2; ei++) {
            uint32_t vhf[4];
            ldsm4(vhf, sb + C2SZ + (uint32_t)(ei * 16 + (lane & 15)) * C2P + cb);
            #pragma unroll
            for (int pick = 0; pick < 2; pick++) {
                int nt = ei * 2 + pick;
                #pragma unroll
                for (int mi = 0; mi < 2; mi++)
                    mma_fp16_2(acc[mi][nt], shf[mi], vhf[pick], vhf[pick + 2]);
            }
        }
    }

    // reduce across 8 warps via smem (overlays stages)
    __syncthreads();
    float* stage = (float*)smem + w * 1056;    // 32 x 33 per warp
    #pragma unroll
    for (int mi = 0; mi < 2; mi++)
        #pragma unroll
        for (int nt = 0; nt < 4; nt++) {
            int r0 = mi * 16 + (lane >> 2);
            int c0 = nt * 8 + (lane & 3) * 2;
            stage[r0 * 33 + c0]           = acc[mi][nt][0];
            stage[r0 * 33 + c0 + 1]       = acc[mi][nt][1];
            stage[(r0 + 8) * 33 + c0]     = acc[mi][nt][2];
            stage[(r0 + 8) * 33 + c0 + 1] = acc[mi][nt][3];
        }
    __syncthreads();
    {
        float* basep = (float*)smem;
        int j0 = tid * 4;
        int d = j0 >> 5, e = j0 & 31;
        float4 s = make_float4(0.f, 0.f, 0.f, 0.f);
        #pragma unroll
        for (int ww = 0; ww < 8; ww++) {
            float* p2 = basep + ww * 1056 + d * 33 + e;
            s.x += p2[0]; s.y += p2[1]; s.z += p2[2]; s.w += p2[3];
        }
        *(float4*)(ctxp + ((size_t)chunk * 256 + bh) * 1024 + j0) = s;
    }
}

// ---------------------------------------------------------------------------
// fused weight: ctx = (sum_c P_c) / z, Wf = w_out(head slice) @ ctx^T -> fp16
// Vectorized z + ctx reductions AND o-range split over gridDim.z=4
// (1024 blocks, 64 o-rows each).
// ---------------------------------------------------------------------------
__global__ void __launch_bounds__(256) k_wf(const float* __restrict__ w_out,
                                            const float* __restrict__ ctxp,
                                            const float* __restrict__ zp,
                                            __half* __restrict__ wfh) {
    int head = blockIdx.x, bi = blockIdx.y;
    int bh = bi * HEADS + head;
    int o_base = blockIdx.z * 64;
    __shared__ float cs[DH][33];
    __shared__ float z_s[DH];
    int tid = threadIdx.x;

    // z: 32 rows x 32 chunk-partials; 8 threads/row, float4 each + shfl reduce
    {
        int r = tid >> 3, c4 = (tid & 7) * 4;
        const float* zr = zp + ((size_t)bi * 256 + head * DH + r) * 32 + c4;
        float4 v = *(const float4*)zr;
        float s = v.x + v.y + v.z + v.w;
        s += __shfl_xor_sync(0xffffffffu, s, 1);
        s += __shfl_xor_sync(0xffffffffu, s, 2);
        s += __shfl_xor_sync(0xffffffffu, s, 4);
        if ((tid & 7) == 0) z_s[r] = s;
    }
    __syncthreads();

    // ctx: sum 4 chunk partials (float4 per thread), divide by z
    {
        int j0 = tid * 4;
        int d = j0 >> 5, e = j0 & 31;
        float4 s = make_float4(0.f, 0.f, 0.f, 0.f);
        #pragma unroll
        for (int c = 0; c < CHUNKS; c++) {
            float4 t = *(const float4*)(ctxp + ((size_t)c * 256 + bh) * 1024 + j0);
            s.x += t.x; s.y += t.y; s.z += t.z; s.w += t.w;
        }
        float inv = 1.0f / z_s[d];
        cs[d][e]     = s.x * inv;
        cs[d][e + 1] = s.y * inv;
        cs[d][e + 2] = s.z * inv;
        cs[d][e + 3] = s.w * inv;
    }
    __syncthreads();

    int d = tid & 31, og = tid >> 5;
    #pragma unroll
    for (int oo = 0; oo < 8; oo++) {
        int o = o_base + oo * 8 + og;
        const float* wrow = w_out + (size_t)o * CH + head * DH;
        float acc = 0.f;
        #pragma unroll
        for (int e = 0; e < DH; e++) acc += wrow[e] * cs[d][e];
        wfh[(size_t)bi * CH * CH + (size_t)o * CH + head * DH + d] = __float2half(acc);
    }
}

// ---------------------------------------------------------------------------
extern "C" void kernel_launch(void* const* d_in, const int* in_sizes, int n_in,
                              void* d_out, int out_size) {
    const float* x     = (const float*)d_in[0];
    const float* w_qkv = (const float*)d_in[1];
    const float* w_out = (const float*)d_in[2];
    const float* b_out = (const float*)d_in[3];
    float* out = (float*)d_out;

    __half *xh, *wh, *qh, *sh, *vh, *wfh;
    float *ctxp, *zp;
    cudaGetSymbolAddress((void**)&xh,   g_xh);
    cudaGetSymbolAddress((void**)&wh,   g_wh);
    cudaGetSymbolAddress((void**)&qh,   g_qh);
    cudaGetSymbolAddress((void**)&sh,   g_sh);
    cudaGetSymbolAddress((void**)&vh,   g_vh);
    cudaGetSymbolAddress((void**)&ctxp, g_ctxp);
    cudaGetSymbolAddress((void**)&zp,   g_zp);
    cudaGetSymbolAddress((void**)&wfh,  g_wfh);

    cudaFuncSetAttribute(k_sgemm<false>, cudaFuncAttributeMaxDynamicSharedMemorySize, SGEMM_SMEM);
    cudaFuncSetAttribute(k_sgemm<true>,  cudaFuncAttributeMaxDynamicSharedMemorySize, SGEMM_SMEM);
    cudaFuncSetAttribute(k_context_tc,   cudaFuncAttributeMaxDynamicSharedMemorySize, CTX2_SMEM);

    // 0. merged splits (single fp16), 8 elems/thread
    int split_blocks = (int)((XELEMS + WELEMS) / 2048);
    k_split_all<<<split_blocks, 256>>>(x, w_qkv, xh, wh);
    // 1. QKV GEMM (1-product); epilogues: q softmax, k exp + z, v
    k_sgemm<false><<<dim3(NPIX / 128, QKV_M / 128, BF), 256, SGEMM_SMEM>>>(
        wh, xh, nullptr, nullptr, qh, sh, vh, zp);
    // 2. tensor-core context partials (1-product, 6-stage)
    k_context_tc<<<dim3(HEADS, BF, CHUNKS), 256, CTX2_SMEM>>>(sh, vh, ctxp);
    // 3. fused weight -> single fp16 (o-range split over z=4)
    k_wf<<<dim3(HEADS, BF, 4), 256>>>(w_out, ctxp, zp, wfh);
    // 4. output GEMM (1-product) + bias + scatter
    k_sgemm<true><<<dim3(NPIX / 128, CH / 128, BF), 256, SGEMM_SMEM>>>(
        wfh, qh, b_out, out, nullptr, nullptr, nullptr, nullptr);
}